// round 14
// baseline (speedup 1.0000x reference)
#include <cuda_runtime.h>
#include <cuda_bf16.h>
#include <mma.h>
#include <math.h>
#include <stdint.h>

using namespace nvcuda;

#define TOKENS 4096
#define HIDDEN 2048
#define INTER  1408
#define NE     16
#define TOPK   2
#define MAXROWS (TOKENS * TOPK)

// ---------------- scratch (R12-proven set) --------------------------------------
__device__ int   g_count[NE];
__device__ int   g_offset[NE + 1];
__device__ int   g_te[TOKENS * TOPK];
__device__ float g_tw[TOKENS * TOPK];
__device__ int   g_tok[MAXROWS];
__device__ float g_w[MAXROWS];
__device__ __align__(128) __nv_bfloat16 g_hhi[(size_t)TOKENS * HIDDEN];
__device__ __align__(128) __nv_bfloat16 g_hlo[(size_t)TOKENS * HIDDEN];
__device__ __align__(128) __nv_bfloat16 g_ahi[(size_t)MAXROWS * INTER];
__device__ __align__(128) __nv_bfloat16 g_alo[(size_t)MAXROWS * INTER];

// ---------------- helpers ------------------------------------------------------
__device__ __forceinline__ void split4s(float4 v,
                                        __nv_bfloat16* hp, __nv_bfloat16* lp) {
    __nv_bfloat162 h01 = __floats2bfloat162_rn(v.x, v.y);
    __nv_bfloat162 h23 = __floats2bfloat162_rn(v.z, v.w);
    float2 f01 = __bfloat1622float2(h01);
    float2 f23 = __bfloat1622float2(h23);
    __nv_bfloat162 l01 = __floats2bfloat162_rn(v.x - f01.x, v.y - f01.y);
    __nv_bfloat162 l23 = __floats2bfloat162_rn(v.z - f23.x, v.w - f23.y);
    *(uint2*)hp = make_uint2(*(uint32_t*)&h01, *(uint32_t*)&h23);
    *(uint2*)lp = make_uint2(*(uint32_t*)&l01, *(uint32_t*)&l23);
}

typedef wmma::fragment<wmma::matrix_a, 16, 16, 16, __nv_bfloat16, wmma::row_major> FragA;
typedef wmma::fragment<wmma::matrix_b, 16, 16, 16, __nv_bfloat16, wmma::row_major> FragB;
typedef wmma::fragment<wmma::accumulator, 16, 16, 16, float> FragC;

// ---------------- kernel 0: routing ---------------------------------------------
__global__ void route_kernel(const float* __restrict__ logits) {
    int t = blockIdx.x * blockDim.x + threadIdx.x;
    if (t >= TOKENS) return;
    const float* l = logits + (size_t)t * NE;
    int i0 = 0; float m0 = l[0];
#pragma unroll
    for (int i = 1; i < NE; i++) { float x = l[i]; if (x > m0) { m0 = x; i0 = i; } }
    int i1 = (i0 == 0) ? 1 : 0; float m1 = l[i1];
#pragma unroll
    for (int i = 0; i < NE; i++) {
        if (i == i0) continue;
        float x = l[i];
        if (x > m1) { m1 = x; i1 = i; }
    }
    float e  = expf(m1 - m0);
    float w0 = 1.0f / (1.0f + e);
    float w1 = e * w0;
    g_te[t * 2 + 0] = i0;  g_tw[t * 2 + 0] = w0;
    g_te[t * 2 + 1] = i1;  g_tw[t * 2 + 1] = w1;
}

// ---------------- kernel 1: count + scan + place (one block) --------------------
__global__ __launch_bounds__(1024) void scanplace_kernel() {
    __shared__ int s_cnt[NE], s_off[NE], s_cur[NE];
    const int tid = threadIdx.x;
    if (tid < NE) s_cnt[tid] = 0;
    __syncthreads();
    for (int i = tid; i < MAXROWS; i += 1024) atomicAdd(&s_cnt[g_te[i]], 1);
    __syncthreads();
    if (tid == 0) {
        int acc = 0;
        for (int e = 0; e < NE; e++) {
            s_off[e] = acc;
            g_count[e]  = s_cnt[e];
            g_offset[e] = acc;
            acc += s_cnt[e];
        }
        g_offset[NE] = acc;
    }
    __syncthreads();
    if (tid < NE) s_cur[tid] = 0;
    __syncthreads();
    for (int i = tid; i < MAXROWS; i += 1024) {
        int e = g_te[i];
        int pos = atomicAdd(&s_cur[e], 1);
        int idx = s_off[e] + pos;
        g_tok[idx] = i >> 1;
        g_w[idx]   = g_tw[i];
    }
}

// ---------------- kernel 2: hidden fp32 -> bf16 hi/lo ----------------------------
__global__ void conv_hidden(const float4* __restrict__ src) {
    int i = blockIdx.x * blockDim.x + threadIdx.x;
    if (i >= TOKENS * HIDDEN / 4) return;
    float4 v = src[i];
    __nv_bfloat162 h01 = __floats2bfloat162_rn(v.x, v.y);
    __nv_bfloat162 h23 = __floats2bfloat162_rn(v.z, v.w);
    float2 f01 = __bfloat1622float2(h01);
    float2 f23 = __bfloat1622float2(h23);
    ((__nv_bfloat162*)g_hhi)[2 * i]     = h01;
    ((__nv_bfloat162*)g_hhi)[2 * i + 1] = h23;
    ((__nv_bfloat162*)g_hlo)[2 * i]     = __floats2bfloat162_rn(v.x - f01.x, v.y - f01.y);
    ((__nv_bfloat162*)g_hlo)[2 * i + 1] = __floats2bfloat162_rn(v.z - f23.x, v.w - f23.y);
}

__global__ void zero_kernel(float* __restrict__ out) {
    int i = blockIdx.x * blockDim.x + threadIdx.x;
    if (i < TOKENS * HIDDEN) out[i] = 0.0f;
}

// ================ GEMM1: gate+up, 128 thr, warp tile 64x32/matrix ===============
// 4 warps: 2(m) x 2(n). BM=128, BN=64, BK=16, 2-stage, 2 CTAs/SM (256 reg budget).
#define LDA 24
#define LDB 72
#define G1_STG  21504
#define G1_SMEM (512 + 2 * G1_STG)

__global__ __launch_bounds__(128, 2) void gemm1_wmma(
    const float* __restrict__ wg,
    const float* __restrict__ wu)
{
    const int e   = blockIdx.z;
    const int cnt = g_count[e];
    const int m0  = blockIdx.y * 128;
    if (m0 >= cnt) return;
    const int n0   = blockIdx.x * 64;
    const int base = g_offset[e];

    extern __shared__ char sm[];
    int* toks = (int*)sm;

    const int tid  = threadIdx.x;
    const int wid  = tid >> 5, lane = tid & 31;
    const int wm   = (wid & 1) * 64;       // 0 or 64
    const int wn   = (wid >> 1) * 32;      // 0 or 32

    if (tid < 128) {
        int r = m0 + tid;
        toks[tid] = g_tok[base + ((r < cnt) ? r : 0)];
    }
    __syncthreads();

    FragC accg[4][2], accu[4][2];
#pragma unroll
    for (int mt = 0; mt < 4; mt++)
#pragma unroll
        for (int nt = 0; nt < 2; nt++) {
            wmma::fill_fragment(accg[mt][nt], 0.0f);
            wmma::fill_fragment(accu[mt][nt], 0.0f);
        }

    // A loader: row = tid (0..127), both 8-elem chunks hi/lo
    const size_t arowoff = (size_t)toks[tid] * HIDDEN;
    // B loader: brow = tid>>3 (0..15), 8 fp32 cols per matrix
    const int brow = tid >> 3, bc8 = (tid & 7) * 8;

    uint4 pfAh0, pfAh1, pfAl0, pfAl1;
    float4 pfG0, pfG1, pfU0, pfU1;

    auto LOADG = [&](int k0) {
        pfAh0 = *(const uint4*)(g_hhi + arowoff + k0);
        pfAh1 = *(const uint4*)(g_hhi + arowoff + k0 + 8);
        pfAl0 = *(const uint4*)(g_hlo + arowoff + k0);
        pfAl1 = *(const uint4*)(g_hlo + arowoff + k0 + 8);
        size_t off = (size_t)e * HIDDEN * INTER + (size_t)(k0 + brow) * INTER + n0 + bc8;
        pfG0 = *(const float4*)(wg + off);
        pfG1 = *(const float4*)(wg + off + 4);
        pfU0 = *(const float4*)(wu + off);
        pfU1 = *(const float4*)(wu + off + 4);
    };
    auto STORES = [&](int b) {
        char* st = sm + 512 + b * G1_STG;
        __nv_bfloat16* Ahi = (__nv_bfloat16*)(st);
        __nv_bfloat16* Alo = (__nv_bfloat16*)(st + 6144);
        __nv_bfloat16* Bgh = (__nv_bfloat16*)(st + 12288);
        __nv_bfloat16* Bgl = (__nv_bfloat16*)(st + 14592);
        __nv_bfloat16* Buh = (__nv_bfloat16*)(st + 16896);
        __nv_bfloat16* Bul = (__nv_bfloat16*)(st + 19200);
        *(uint4*)(Ahi + tid * LDA)     = pfAh0;
        *(uint4*)(Ahi + tid * LDA + 8) = pfAh1;
        *(uint4*)(Alo + tid * LDA)     = pfAl0;
        *(uint4*)(Alo + tid * LDA + 8) = pfAl1;
        split4s(pfG0, Bgh + brow * LDB + bc8,     Bgl + brow * LDB + bc8);
        split4s(pfG1, Bgh + brow * LDB + bc8 + 4, Bgl + brow * LDB + bc8 + 4);
        split4s(pfU0, Buh + brow * LDB + bc8,     Bul + brow * LDB + bc8);
        split4s(pfU1, Buh + brow * LDB + bc8 + 4, Bul + brow * LDB + bc8 + 4);
    };

    const int NS = HIDDEN / 16;   // 128
    LOADG(0);
    STORES(0);
    LOADG(16);
    __syncthreads();

    for (int s = 0; s < NS; s++) {
        if (s + 1 < NS) STORES((s + 1) & 1);
        if (s + 2 < NS) LOADG((s + 2) * 16);

        const char* st = sm + 512 + (s & 1) * G1_STG;
        const __nv_bfloat16* Ahi = (const __nv_bfloat16*)(st);
        const __nv_bfloat16* Alo = (const __nv_bfloat16*)(st + 6144);
        const __nv_bfloat16* Bgh = (const __nv_bfloat16*)(st + 12288);
        const __nv_bfloat16* Bgl = (const __nv_bfloat16*)(st + 14592);
        const __nv_bfloat16* Buh = (const __nv_bfloat16*)(st + 16896);
        const __nv_bfloat16* Bul = (const __nv_bfloat16*)(st + 19200);

        // hold all B fragments for this warp's two n-tiles
        FragB bgh[2], bgl[2], buh[2], bul[2];
#pragma unroll
        for (int nt = 0; nt < 2; nt++) {
            const int bcol = wn + nt * 16;
            wmma::load_matrix_sync(bgh[nt], Bgh + bcol, LDB);
            wmma::load_matrix_sync(bgl[nt], Bgl + bcol, LDB);
            wmma::load_matrix_sync(buh[nt], Buh + bcol, LDB);
            wmma::load_matrix_sync(bul[nt], Bul + bcol, LDB);
        }
        // stream A fragments over 4 m-tiles
#pragma unroll
        for (int mt = 0; mt < 4; mt++) {
            FragA ah, al;
            wmma::load_matrix_sync(ah, Ahi + (wm + mt * 16) * LDA, LDA);
            wmma::load_matrix_sync(al, Alo + (wm + mt * 16) * LDA, LDA);
#pragma unroll
            for (int nt = 0; nt < 2; nt++) {
                wmma::mma_sync(accg[mt][nt], ah, bgh[nt], accg[mt][nt]);
                wmma::mma_sync(accg[mt][nt], al, bgh[nt], accg[mt][nt]);
                wmma::mma_sync(accg[mt][nt], ah, bgl[nt], accg[mt][nt]);
                wmma::mma_sync(accu[mt][nt], ah, buh[nt], accu[mt][nt]);
                wmma::mma_sync(accu[mt][nt], al, buh[nt], accu[mt][nt]);
                wmma::mma_sync(accu[mt][nt], ah, bul[nt], accu[mt][nt]);
            }
        }
        __syncthreads();
    }

    // epilogue: swiglu + bf16 hi/lo activation store (per-warp staging)
    float* stg = (float*)(sm + 512) + wid * 320;   // 16x20 per warp
#pragma unroll
    for (int mt = 0; mt < 4; mt++)
#pragma unroll
        for (int nt = 0; nt < 2; nt++) {
            FragC& G = accg[mt][nt];
            FragC& U = accu[mt][nt];
#pragma unroll
            for (int i = 0; i < G.num_elements; i++) {
                float g = G.x[i];
                G.x[i] = (g / (1.0f + __expf(-g))) * U.x[i];
            }
            wmma::store_matrix_sync(stg, G, 20, wmma::mem_row_major);
            __syncwarp();
            for (int i = lane; i < 128; i += 32) {
                int r = i >> 3, c = (i & 7) * 2;
                int m = m0 + wm + mt * 16 + r;
                if (m < cnt) {
                    float a0 = stg[r * 20 + c], a1 = stg[r * 20 + c + 1];
                    __nv_bfloat162 hv = __floats2bfloat162_rn(a0, a1);
                    float2 hf = __bfloat1622float2(hv);
                    __nv_bfloat162 lv = __floats2bfloat162_rn(a0 - hf.x, a1 - hf.y);
                    size_t off = (size_t)(base + m) * INTER + n0 + wn + nt * 16 + c;
                    *(__nv_bfloat162*)(g_ahi + off) = hv;
                    *(__nv_bfloat162*)(g_alo + off) = lv;
                }
            }
            __syncwarp();
        }
}

// ================ GEMM2: down (R12-proven), BN=128, BK=16, 2 CTAs/SM ============
#define LDB2 136
#define G2_STG  20992
#define G2_SMEM (2 * G2_STG)

__global__ __launch_bounds__(256, 2) void gemm2_wmma(
    const float* __restrict__ wd, float* __restrict__ out)
{
    const int e   = blockIdx.z;
    const int cnt = g_count[e];
    const int m0  = blockIdx.y * 128;
    if (m0 >= cnt) return;
    const int n0   = blockIdx.x * 128;
    const int base = g_offset[e];

    extern __shared__ char sm[];

    const int tid  = threadIdx.x;
    const int wid  = tid >> 5, lane = tid & 31;
    const int wm   = (wid & 3) * 32;
    const int wn   = (wid >> 2) * 64;

    const int ar = tid >> 1;
    const int aq = (tid & 1) * 8;
    int arm = m0 + ar;
    const int arow = base + ((arm < cnt) ? arm : 0);
    const int brow = tid >> 4, bc8 = (tid & 15) * 8;

    FragC acc[2][4];
#pragma unroll
    for (int mt = 0; mt < 2; mt++)
#pragma unroll
        for (int nt = 0; nt < 4; nt++) wmma::fill_fragment(acc[mt][nt], 0.0f);

    uint4 pfAh, pfAl;
    float4 pfB0, pfB1;

    auto LOADG = [&](int k0) {
        size_t off = (size_t)arow * INTER + k0 + aq;
        pfAh = *(const uint4*)(g_ahi + off);
        pfAl = *(const uint4*)(g_alo + off);
        const float* bsrc = wd + (size_t)e * INTER * HIDDEN + (size_t)(k0 + brow) * HIDDEN + n0 + bc8;
        pfB0 = *(const float4*)(bsrc);
        pfB1 = *(const float4*)(bsrc + 4);
    };
    auto STORES = [&](int b) {
        char* st = sm + b * G2_STG;
        __nv_bfloat16* Ahi = (__nv_bfloat16*)(st);
        __nv_bfloat16* Alo = (__nv_bfloat16*)(st + 6144);
        __nv_bfloat16* Bh  = (__nv_bfloat16*)(st + 12288);
        __nv_bfloat16* Bl  = (__nv_bfloat16*)(st + 16640);
        *(uint4*)(Ahi + ar * LDA + aq) = pfAh;
        *(uint4*)(Alo + ar * LDA + aq) = pfAl;
        split4s(pfB0, Bh + brow * LDB2 + bc8,     Bl + brow * LDB2 + bc8);
        split4s(pfB1, Bh + brow * LDB2 + bc8 + 4, Bl + brow * LDB2 + bc8 + 4);
    };

    const int NS = INTER / 16;   // 88
    LOADG(0);
    STORES(0);
    LOADG(16);
    __syncthreads();

    for (int s = 0; s < NS; s++) {
        if (s + 1 < NS) STORES((s + 1) & 1);
        if (s + 2 < NS) LOADG((s + 2) * 16);

        const char* st = sm + (s & 1) * G2_STG;
        const __nv_bfloat16* Ahi = (const __nv_bfloat16*)(st);
        const __nv_bfloat16* Alo = (const __nv_bfloat16*)(st + 6144);
        const __nv_bfloat16* Bh  = (const __nv_bfloat16*)(st + 12288);
        const __nv_bfloat16* Bl  = (const __nv_bfloat16*)(st + 16640);

        FragA ah[2], al[2];
#pragma unroll
        for (int mt = 0; mt < 2; mt++) {
            wmma::load_matrix_sync(ah[mt], Ahi + (wm + mt * 16) * LDA, LDA);
            wmma::load_matrix_sync(al[mt], Alo + (wm + mt * 16) * LDA, LDA);
        }
#pragma unroll
        for (int nt = 0; nt < 4; nt++) {
            FragB bh, bl;
            const int bcol = wn + nt * 16;
            wmma::load_matrix_sync(bh, Bh + bcol, LDB2);
            wmma::load_matrix_sync(bl, Bl + bcol, LDB2);
#pragma unroll
            for (int mt = 0; mt < 2; mt++) {
                wmma::mma_sync(acc[mt][nt], ah[mt], bh, acc[mt][nt]);
                wmma::mma_sync(acc[mt][nt], al[mt], bh, acc[mt][nt]);
                wmma::mma_sync(acc[mt][nt], ah[mt], bl, acc[mt][nt]);
            }
        }
        __syncthreads();
    }

    // weighted scatter via per-warp staging
    float* stg = (float*)sm + wid * 320;
#pragma unroll
    for (int mt = 0; mt < 2; mt++)
#pragma unroll
        for (int nt = 0; nt < 4; nt++) {
            wmma::store_matrix_sync(stg, acc[mt][nt], 20, wmma::mem_row_major);
            __syncwarp();
            for (int i = lane; i < 256; i += 32) {
                int r = i >> 4, c = i & 15;
                int m = m0 + wm + mt * 16 + r;
                if (m < cnt) {
                    int   t = g_tok[base + m];
                    float w = g_w[base + m];
                    atomicAdd(out + (size_t)t * HIDDEN + n0 + wn + nt * 16 + c,
                              w * stg[r * 20 + c]);
                }
            }
            __syncwarp();
        }
}

// ---------------- launch ------------------------------------------------------------
extern "C" void kernel_launch(void* const* d_in, const int* in_sizes, int n_in,
                              void* d_out, int out_size) {
    (void)in_sizes; (void)n_in; (void)out_size;
    const float* hidden = (const float*)d_in[0];
    const float* logits = (const float*)d_in[1];
    const float* wg     = (const float*)d_in[2];
    const float* wu     = (const float*)d_in[3];
    const float* wd     = (const float*)d_in[4];
    float* out = (float*)d_out;

    route_kernel<<<(TOKENS + 255) / 256, 256>>>(logits);                  // 0
    scanplace_kernel<<<1, 1024>>>();                                      // 1
    conv_hidden<<<(TOKENS * HIDDEN / 4 + 255) / 256, 256>>>((const float4*)hidden); // 2

    dim3 g1(INTER / 64, (TOKENS + 127) / 128, NE);    // (22, 32, 16)
    gemm1_wmma<<<g1, 128, G1_SMEM>>>(wg, wu);                             // 3 (profiled)

    zero_kernel<<<(TOKENS * HIDDEN + 255) / 256, 256>>>(out);             // 4
    dim3 g2(HIDDEN / 128, (TOKENS + 127) / 128, NE);  // (16, 32, 16)
    gemm2_wmma<<<g2, 256, G2_SMEM>>>(wd, out);                            // 5
}

// round 15
// speedup vs baseline: 1.0381x; 1.0381x over previous
#include <cuda_runtime.h>
#include <cuda_bf16.h>
#include <mma.h>
#include <math.h>
#include <stdint.h>

using namespace nvcuda;

#define TOKENS 4096
#define HIDDEN 2048
#define INTER  1408
#define NE     16
#define TOPK   2
#define MAXROWS (TOKENS * TOPK)
#define PADROWS (MAXROWS + NE * 128)   // per-expert 128-padded row space

// ---------------- scratch ----------------------------------------------------
__device__ int   g_count[NE];
__device__ int   g_offset[NE + 1];
__device__ int   g_te[TOKENS * TOPK];
__device__ float g_tw[TOKENS * TOPK];
__device__ int   g_tok[PADROWS];
__device__ float g_w[PADROWS];
__device__ int   g_rowof[TOKENS * TOPK];
__device__ __align__(128) __nv_bfloat16 g_hhi[(size_t)TOKENS * HIDDEN];
__device__ __align__(128) __nv_bfloat16 g_hlo[(size_t)TOKENS * HIDDEN];
__device__ __align__(128) __nv_bfloat16 g_ahi[(size_t)PADROWS * INTER];
__device__ __align__(128) __nv_bfloat16 g_alo[(size_t)PADROWS * INTER];
__device__ __align__(128) float g_y[(size_t)PADROWS * HIDDEN];

// ---------------- helpers ------------------------------------------------------
__device__ __forceinline__ void split4s(float4 v,
                                        __nv_bfloat16* hp, __nv_bfloat16* lp) {
    __nv_bfloat162 h01 = __floats2bfloat162_rn(v.x, v.y);
    __nv_bfloat162 h23 = __floats2bfloat162_rn(v.z, v.w);
    float2 f01 = __bfloat1622float2(h01);
    float2 f23 = __bfloat1622float2(h23);
    __nv_bfloat162 l01 = __floats2bfloat162_rn(v.x - f01.x, v.y - f01.y);
    __nv_bfloat162 l23 = __floats2bfloat162_rn(v.z - f23.x, v.w - f23.y);
    *(uint2*)hp = make_uint2(*(uint32_t*)&h01, *(uint32_t*)&h23);
    *(uint2*)lp = make_uint2(*(uint32_t*)&l01, *(uint32_t*)&l23);
}

typedef wmma::fragment<wmma::matrix_a, 16, 16, 16, __nv_bfloat16, wmma::row_major> FragA;
typedef wmma::fragment<wmma::matrix_b, 16, 16, 16, __nv_bfloat16, wmma::row_major> FragB;
typedef wmma::fragment<wmma::accumulator, 16, 16, 16, float> FragC;

// ---------------- kernel 0: routing ---------------------------------------------
__global__ void route_kernel(const float* __restrict__ logits) {
    int t = blockIdx.x * blockDim.x + threadIdx.x;
    if (t >= TOKENS) return;
    const float* l = logits + (size_t)t * NE;
    int i0 = 0; float m0 = l[0];
#pragma unroll
    for (int i = 1; i < NE; i++) { float x = l[i]; if (x > m0) { m0 = x; i0 = i; } }
    int i1 = (i0 == 0) ? 1 : 0; float m1 = l[i1];
#pragma unroll
    for (int i = 0; i < NE; i++) {
        if (i == i0) continue;
        float x = l[i];
        if (x > m1) { m1 = x; i1 = i; }
    }
    float e  = expf(m1 - m0);
    float w0 = 1.0f / (1.0f + e);
    float w1 = e * w0;
    g_te[t * 2 + 0] = i0;  g_tw[t * 2 + 0] = w0;
    g_te[t * 2 + 1] = i1;  g_tw[t * 2 + 1] = w1;
}

// ---------------- kernel 1: count + padded scan + place --------------------------
__global__ __launch_bounds__(1024) void scanplace_kernel() {
    __shared__ int s_cnt[NE], s_off[NE], s_cur[NE];
    const int tid = threadIdx.x;
    if (tid < NE) s_cnt[tid] = 0;
    __syncthreads();
    for (int i = tid; i < MAXROWS; i += 1024) atomicAdd(&s_cnt[g_te[i]], 1);
    __syncthreads();
    if (tid == 0) {
        int acc = 0;
        for (int e = 0; e < NE; e++) {
            s_off[e] = acc;
            g_count[e]  = s_cnt[e];
            g_offset[e] = acc;
            acc += (s_cnt[e] + 127) & ~127;
        }
        g_offset[NE] = acc;
    }
    __syncthreads();
    if (tid < NE) s_cur[tid] = 0;
    __syncthreads();
    for (int i = tid; i < MAXROWS; i += 1024) {
        int e = g_te[i];
        int pos = atomicAdd(&s_cur[e], 1);
        int idx = s_off[e] + pos;
        g_tok[idx]   = i >> 1;
        g_w[idx]     = g_tw[i];
        g_rowof[i]   = idx;
    }
}

// ---------------- kernel 2: hidden fp32 -> bf16 hi/lo ----------------------------
__global__ void conv_hidden(const float4* __restrict__ src) {
    int i = blockIdx.x * blockDim.x + threadIdx.x;
    if (i >= TOKENS * HIDDEN / 4) return;
    float4 v = src[i];
    __nv_bfloat162 h01 = __floats2bfloat162_rn(v.x, v.y);
    __nv_bfloat162 h23 = __floats2bfloat162_rn(v.z, v.w);
    float2 f01 = __bfloat1622float2(h01);
    float2 f23 = __bfloat1622float2(h23);
    ((__nv_bfloat162*)g_hhi)[2 * i]     = h01;
    ((__nv_bfloat162*)g_hhi)[2 * i + 1] = h23;
    ((__nv_bfloat162*)g_hlo)[2 * i]     = __floats2bfloat162_rn(v.x - f01.x, v.y - f01.y);
    ((__nv_bfloat162*)g_hlo)[2 * i + 1] = __floats2bfloat162_rn(v.z - f23.x, v.w - f23.y);
}

// ================ GEMM1: gate+up (R12-proven), 256 thr, BK=16, 2 CTAs/SM ========
#define LDA 24
#define LDB 72
#define G1_STG  21504
#define G1_SMEM (512 + 2 * G1_STG)

__global__ __launch_bounds__(256, 2) void gemm1_wmma(
    const float* __restrict__ wg,
    const float* __restrict__ wu)
{
    const int e   = blockIdx.z;
    const int cnt = g_count[e];
    const int m0  = blockIdx.y * 128;
    if (m0 >= cnt) return;
    const int n0   = blockIdx.x * 64;
    const int base = g_offset[e];

    extern __shared__ char sm[];
    int* toks = (int*)sm;

    const int tid  = threadIdx.x;
    const int wid  = tid >> 5, lane = tid & 31;
    const int wm   = (wid & 3) * 32;
    const int wn   = (wid >> 2) * 32;

    if (tid < 128) {
        int r = m0 + tid;
        toks[tid] = g_tok[base + ((r < cnt) ? r : 0)];
    }
    __syncthreads();

    FragC accg[2][2], accu[2][2];
#pragma unroll
    for (int mt = 0; mt < 2; mt++)
#pragma unroll
        for (int nt = 0; nt < 2; nt++) {
            wmma::fill_fragment(accg[mt][nt], 0.0f);
            wmma::fill_fragment(accu[mt][nt], 0.0f);
        }

    const int ar = tid >> 1;
    const int aq = (tid & 1) * 8;
    const size_t arowoff = (size_t)toks[ar] * HIDDEN + aq;
    const int brow = tid >> 4, bc4 = (tid & 15) * 4;

    uint4 pfAh, pfAl;
    float4 pfG, pfU;

    auto LOADG = [&](int k0) {
        pfAh = *(const uint4*)(g_hhi + arowoff + k0);
        pfAl = *(const uint4*)(g_hlo + arowoff + k0);
        size_t off = (size_t)e * HIDDEN * INTER + (size_t)(k0 + brow) * INTER + n0 + bc4;
        pfG = *(const float4*)(wg + off);
        pfU = *(const float4*)(wu + off);
    };
    auto STORES = [&](int b) {
        char* st = sm + 512 + b * G1_STG;
        __nv_bfloat16* Ahi = (__nv_bfloat16*)(st);
        __nv_bfloat16* Alo = (__nv_bfloat16*)(st + 6144);
        __nv_bfloat16* Bgh = (__nv_bfloat16*)(st + 12288);
        __nv_bfloat16* Bgl = (__nv_bfloat16*)(st + 14592);
        __nv_bfloat16* Buh = (__nv_bfloat16*)(st + 16896);
        __nv_bfloat16* Bul = (__nv_bfloat16*)(st + 19200);
        *(uint4*)(Ahi + ar * LDA + aq) = pfAh;
        *(uint4*)(Alo + ar * LDA + aq) = pfAl;
        split4s(pfG, Bgh + brow * LDB + bc4, Bgl + brow * LDB + bc4);
        split4s(pfU, Buh + brow * LDB + bc4, Bul + brow * LDB + bc4);
    };

    const int NS = HIDDEN / 16;   // 128
    LOADG(0);
    STORES(0);
    LOADG(16);
    __syncthreads();

    for (int s = 0; s < NS; s++) {
        if (s + 1 < NS) STORES((s + 1) & 1);
        if (s + 2 < NS) LOADG((s + 2) * 16);

        const char* st = sm + 512 + (s & 1) * G1_STG;
        const __nv_bfloat16* Ahi = (const __nv_bfloat16*)(st);
        const __nv_bfloat16* Alo = (const __nv_bfloat16*)(st + 6144);
        const __nv_bfloat16* Bgh = (const __nv_bfloat16*)(st + 12288);
        const __nv_bfloat16* Bgl = (const __nv_bfloat16*)(st + 14592);
        const __nv_bfloat16* Buh = (const __nv_bfloat16*)(st + 16896);
        const __nv_bfloat16* Bul = (const __nv_bfloat16*)(st + 19200);

        FragA ah[2], al[2];
#pragma unroll
        for (int mt = 0; mt < 2; mt++) {
            wmma::load_matrix_sync(ah[mt], Ahi + (wm + mt * 16) * LDA, LDA);
            wmma::load_matrix_sync(al[mt], Alo + (wm + mt * 16) * LDA, LDA);
        }
#pragma unroll
        for (int nt = 0; nt < 2; nt++) {
            FragB bh, bl;
            const int bcol = wn + nt * 16;
            wmma::load_matrix_sync(bh, Bgh + bcol, LDB);
            wmma::load_matrix_sync(bl, Bgl + bcol, LDB);
#pragma unroll
            for (int mt = 0; mt < 2; mt++) {
                wmma::mma_sync(accg[mt][nt], ah[mt], bh, accg[mt][nt]);
                wmma::mma_sync(accg[mt][nt], al[mt], bh, accg[mt][nt]);
                wmma::mma_sync(accg[mt][nt], ah[mt], bl, accg[mt][nt]);
            }
            wmma::load_matrix_sync(bh, Buh + bcol, LDB);
            wmma::load_matrix_sync(bl, Bul + bcol, LDB);
#pragma unroll
            for (int mt = 0; mt < 2; mt++) {
                wmma::mma_sync(accu[mt][nt], ah[mt], bh, accu[mt][nt]);
                wmma::mma_sync(accu[mt][nt], al[mt], bh, accu[mt][nt]);
                wmma::mma_sync(accu[mt][nt], ah[mt], bl, accu[mt][nt]);
            }
        }
        __syncthreads();
    }

    float* stg = (float*)(sm + 512) + wid * 320;
#pragma unroll
    for (int mt = 0; mt < 2; mt++)
#pragma unroll
        for (int nt = 0; nt < 2; nt++) {
            FragC& G = accg[mt][nt];
            FragC& U = accu[mt][nt];
#pragma unroll
            for (int i = 0; i < G.num_elements; i++) {
                float g = G.x[i];
                G.x[i] = (g / (1.0f + __expf(-g))) * U.x[i];
            }
            wmma::store_matrix_sync(stg, G, 20, wmma::mem_row_major);
            __syncwarp();
            for (int i = lane; i < 128; i += 32) {
                int r = i >> 3, c = (i & 7) * 2;
                int m = m0 + wm + mt * 16 + r;
                if (m < cnt) {
                    float a0 = stg[r * 20 + c], a1 = stg[r * 20 + c + 1];
                    __nv_bfloat162 hv = __floats2bfloat162_rn(a0, a1);
                    float2 hf = __bfloat1622float2(hv);
                    __nv_bfloat162 lv = __floats2bfloat162_rn(a0 - hf.x, a1 - hf.y);
                    size_t off = (size_t)(base + m) * INTER + n0 + wn + nt * 16 + c;
                    *(__nv_bfloat162*)(g_ahi + off) = hv;
                    *(__nv_bfloat162*)(g_alo + off) = lv;
                }
            }
            __syncwarp();
        }
}

// ================ GEMM2: down (R12-proven mainloop) + direct g_y stores =========
#define LDB2 136
#define G2_STG  20992
#define G2_SMEM (2 * G2_STG)

__global__ __launch_bounds__(256, 2) void gemm2_wmma(const float* __restrict__ wd)
{
    const int e   = blockIdx.z;
    const int cnt = g_count[e];
    const int m0  = blockIdx.y * 128;
    if (m0 >= cnt) return;
    const int n0   = blockIdx.x * 128;
    const int base = g_offset[e];

    extern __shared__ char sm[];

    const int tid  = threadIdx.x;
    const int wid  = tid >> 5;
    const int wm   = (wid & 3) * 32;
    const int wn   = (wid >> 2) * 64;

    const int ar = tid >> 1;
    const int aq = (tid & 1) * 8;
    int arm = m0 + ar;
    const int arow = base + ((arm < cnt) ? arm : 0);
    const int brow = tid >> 4, bc8 = (tid & 15) * 8;

    FragC acc[2][4];
#pragma unroll
    for (int mt = 0; mt < 2; mt++)
#pragma unroll
        for (int nt = 0; nt < 4; nt++) wmma::fill_fragment(acc[mt][nt], 0.0f);

    uint4 pfAh, pfAl;
    float4 pfB0, pfB1;

    auto LOADG = [&](int k0) {
        size_t off = (size_t)arow * INTER + k0 + aq;
        pfAh = *(const uint4*)(g_ahi + off);
        pfAl = *(const uint4*)(g_alo + off);
        const float* bsrc = wd + (size_t)e * INTER * HIDDEN + (size_t)(k0 + brow) * HIDDEN + n0 + bc8;
        pfB0 = *(const float4*)(bsrc);
        pfB1 = *(const float4*)(bsrc + 4);
    };
    auto STORES = [&](int b) {
        char* st = sm + b * G2_STG;
        __nv_bfloat16* Ahi = (__nv_bfloat16*)(st);
        __nv_bfloat16* Alo = (__nv_bfloat16*)(st + 6144);
        __nv_bfloat16* Bh  = (__nv_bfloat16*)(st + 12288);
        __nv_bfloat16* Bl  = (__nv_bfloat16*)(st + 16640);
        *(uint4*)(Ahi + ar * LDA + aq) = pfAh;
        *(uint4*)(Alo + ar * LDA + aq) = pfAl;
        split4s(pfB0, Bh + brow * LDB2 + bc8,     Bl + brow * LDB2 + bc8);
        split4s(pfB1, Bh + brow * LDB2 + bc8 + 4, Bl + brow * LDB2 + bc8 + 4);
    };

    const int NS = INTER / 16;   // 88
    LOADG(0);
    STORES(0);
    LOADG(16);
    __syncthreads();

    for (int s = 0; s < NS; s++) {
        if (s + 1 < NS) STORES((s + 1) & 1);
        if (s + 2 < NS) LOADG((s + 2) * 16);

        const char* st = sm + (s & 1) * G2_STG;
        const __nv_bfloat16* Ahi = (const __nv_bfloat16*)(st);
        const __nv_bfloat16* Alo = (const __nv_bfloat16*)(st + 6144);
        const __nv_bfloat16* Bh  = (const __nv_bfloat16*)(st + 12288);
        const __nv_bfloat16* Bl  = (const __nv_bfloat16*)(st + 16640);

        FragA ah[2], al[2];
#pragma unroll
        for (int mt = 0; mt < 2; mt++) {
            wmma::load_matrix_sync(ah[mt], Ahi + (wm + mt * 16) * LDA, LDA);
            wmma::load_matrix_sync(al[mt], Alo + (wm + mt * 16) * LDA, LDA);
        }
#pragma unroll
        for (int nt = 0; nt < 4; nt++) {
            FragB bh, bl;
            const int bcol = wn + nt * 16;
            wmma::load_matrix_sync(bh, Bh + bcol, LDB2);
            wmma::load_matrix_sync(bl, Bl + bcol, LDB2);
#pragma unroll
            for (int mt = 0; mt < 2; mt++) {
                wmma::mma_sync(acc[mt][nt], ah[mt], bh, acc[mt][nt]);
                wmma::mma_sync(acc[mt][nt], al[mt], bh, acc[mt][nt]);
                wmma::mma_sync(acc[mt][nt], ah[mt], bl, acc[mt][nt]);
            }
        }
        __syncthreads();
    }

    // direct unguarded stores into padded scratch (no atomics, no staging)
#pragma unroll
    for (int mt = 0; mt < 2; mt++)
#pragma unroll
        for (int nt = 0; nt < 4; nt++) {
            float* dst = g_y + (size_t)(base + m0 + wm + mt * 16) * HIDDEN + n0 + wn + nt * 16;
            wmma::store_matrix_sync(dst, acc[mt][nt], HIDDEN, wmma::mem_row_major);
        }
}

// ---------------- kernel: weighted combine out = w0*y[r0] + w1*y[r1] -------------
__global__ void combine_kernel(float* __restrict__ out) {
    int i = blockIdx.x * blockDim.x + threadIdx.x;
    const int H4 = HIDDEN / 4;
    if (i >= TOKENS * H4) return;
    int t  = i / H4;
    int h4 = i - t * H4;
    int r0 = g_rowof[t * 2 + 0];
    int r1 = g_rowof[t * 2 + 1];
    float w0 = g_w[r0], w1 = g_w[r1];
    float4 a = *(const float4*)(g_y + (size_t)r0 * HIDDEN + h4 * 4);
    float4 b = *(const float4*)(g_y + (size_t)r1 * HIDDEN + h4 * 4);
    float4 o;
    o.x = w0 * a.x + w1 * b.x;
    o.y = w0 * a.y + w1 * b.y;
    o.z = w0 * a.z + w1 * b.z;
    o.w = w0 * a.w + w1 * b.w;
    *(float4*)(out + (size_t)t * HIDDEN + h4 * 4) = o;
}

// ---------------- launch ------------------------------------------------------------
extern "C" void kernel_launch(void* const* d_in, const int* in_sizes, int n_in,
                              void* d_out, int out_size) {
    (void)in_sizes; (void)n_in; (void)out_size;
    const float* hidden = (const float*)d_in[0];
    const float* logits = (const float*)d_in[1];
    const float* wg     = (const float*)d_in[2];
    const float* wu     = (const float*)d_in[3];
    const float* wd     = (const float*)d_in[4];
    float* out = (float*)d_out;

    route_kernel<<<(TOKENS + 255) / 256, 256>>>(logits);                  // 0
    scanplace_kernel<<<1, 1024>>>();                                      // 1
    conv_hidden<<<(TOKENS * HIDDEN / 4 + 255) / 256, 256>>>((const float4*)hidden); // 2

    dim3 g1(INTER / 64, (TOKENS + 127) / 128, NE);    // (22, 32, 16)
    gemm1_wmma<<<g1, 256, G1_SMEM>>>(wg, wu);                             // 3 (profiled)

    dim3 g2(HIDDEN / 128, (TOKENS + 127) / 128, NE);  // (16, 32, 16)
    gemm2_wmma<<<g2, 256, G2_SMEM>>>(wd);                                 // 4

    combine_kernel<<<(TOKENS * HIDDEN / 4 + 255) / 256, 256>>>(out);      // 5
}

// round 17
// speedup vs baseline: 1.4650x; 1.4112x over previous
#include <cuda_runtime.h>
#include <cuda_fp16.h>
#include <cuda_bf16.h>
#include <mma.h>
#include <math.h>
#include <stdint.h>

using namespace nvcuda;

#define TOKENS 4096
#define HIDDEN 2048
#define INTER  1408
#define NE     16
#define TOPK   2
#define MAXROWS (TOKENS * TOPK)

// ---------------- scratch ----------------------------------------------------
__device__ int   g_count[NE];
__device__ int   g_offset[NE + 1];
__device__ int   g_te[TOKENS * TOPK];
__device__ float g_tw[TOKENS * TOPK];
__device__ int   g_tok[MAXROWS];
__device__ float g_w[MAXROWS];
// hidden pre-split to fp16 hi/lo (~22-bit mantissa pair)
__device__ __align__(128) __half g_hhi[(size_t)TOKENS * HIDDEN];
__device__ __align__(128) __half g_hlo[(size_t)TOKENS * HIDDEN];
// activations bf16 hi/lo (feed precise bf16x3 GEMM2)
__device__ __align__(128) __nv_bfloat16 g_ahi[(size_t)MAXROWS * INTER];
__device__ __align__(128) __nv_bfloat16 g_alo[(size_t)MAXROWS * INTER];

// ---------------- helpers ------------------------------------------------------
__device__ __forceinline__ void split4s(float4 v,
                                        __nv_bfloat16* hp, __nv_bfloat16* lp) {
    __nv_bfloat162 h01 = __floats2bfloat162_rn(v.x, v.y);
    __nv_bfloat162 h23 = __floats2bfloat162_rn(v.z, v.w);
    float2 f01 = __bfloat1622float2(h01);
    float2 f23 = __bfloat1622float2(h23);
    __nv_bfloat162 l01 = __floats2bfloat162_rn(v.x - f01.x, v.y - f01.y);
    __nv_bfloat162 l23 = __floats2bfloat162_rn(v.z - f23.x, v.w - f23.y);
    *(uint2*)hp = make_uint2(*(uint32_t*)&h01, *(uint32_t*)&h23);
    *(uint2*)lp = make_uint2(*(uint32_t*)&l01, *(uint32_t*)&l23);
}
// fp32x4 -> fp16 (hi only), vectorized 8B store
__device__ __forceinline__ void cvt4h(float4 v, __half* p) {
    __half2 a = __floats2half2_rn(v.x, v.y);
    __half2 b = __floats2half2_rn(v.z, v.w);
    *(uint2*)p = make_uint2(*(uint32_t*)&a, *(uint32_t*)&b);
}

typedef wmma::fragment<wmma::matrix_a, 16, 16, 16, __half, wmma::row_major> HFragA;
typedef wmma::fragment<wmma::matrix_b, 16, 16, 16, __half, wmma::row_major> HFragB;
typedef wmma::fragment<wmma::matrix_a, 16, 16, 16, __nv_bfloat16, wmma::row_major> FragA;
typedef wmma::fragment<wmma::matrix_b, 16, 16, 16, __nv_bfloat16, wmma::row_major> FragB;
typedef wmma::fragment<wmma::accumulator, 16, 16, 16, float> FragC;

// ---------------- kernel 0: routing ---------------------------------------------
__global__ void route_kernel(const float* __restrict__ logits) {
    int t = blockIdx.x * blockDim.x + threadIdx.x;
    if (t >= TOKENS) return;
    const float* l = logits + (size_t)t * NE;
    int i0 = 0; float m0 = l[0];
#pragma unroll
    for (int i = 1; i < NE; i++) { float x = l[i]; if (x > m0) { m0 = x; i0 = i; } }
    int i1 = (i0 == 0) ? 1 : 0; float m1 = l[i1];
#pragma unroll
    for (int i = 0; i < NE; i++) {
        if (i == i0) continue;
        float x = l[i];
        if (x > m1) { m1 = x; i1 = i; }
    }
    float e  = expf(m1 - m0);
    float w0 = 1.0f / (1.0f + e);
    float w1 = e * w0;
    g_te[t * 2 + 0] = i0;  g_tw[t * 2 + 0] = w0;
    g_te[t * 2 + 1] = i1;  g_tw[t * 2 + 1] = w1;
}

// ---------------- kernel 1: count + scan + place (one block) --------------------
__global__ __launch_bounds__(1024) void scanplace_kernel() {
    __shared__ int s_cnt[NE], s_off[NE], s_cur[NE];
    const int tid = threadIdx.x;
    if (tid < NE) s_cnt[tid] = 0;
    __syncthreads();
    for (int i = tid; i < MAXROWS; i += 1024) atomicAdd(&s_cnt[g_te[i]], 1);
    __syncthreads();
    if (tid == 0) {
        int acc = 0;
        for (int e = 0; e < NE; e++) {
            s_off[e] = acc;
            g_count[e]  = s_cnt[e];
            g_offset[e] = acc;
            acc += s_cnt[e];
        }
        g_offset[NE] = acc;
    }
    __syncthreads();
    if (tid < NE) s_cur[tid] = 0;
    __syncthreads();
    for (int i = tid; i < MAXROWS; i += 1024) {
        int e = g_te[i];
        int pos = atomicAdd(&s_cur[e], 1);
        int idx = s_off[e] + pos;
        g_tok[idx] = i >> 1;
        g_w[idx]   = g_tw[i];
    }
}

// ---------------- kernel 2: hidden fp32 -> fp16 hi/lo ----------------------------
__global__ void conv_hidden(const float4* __restrict__ src) {
    int i = blockIdx.x * blockDim.x + threadIdx.x;
    if (i >= TOKENS * HIDDEN / 4) return;
    float4 v = src[i];
    __half2 h01 = __floats2half2_rn(v.x, v.y);
    __half2 h23 = __floats2half2_rn(v.z, v.w);
    float2 f01 = __half22float2(h01);
    float2 f23 = __half22float2(h23);
    ((__half2*)g_hhi)[2 * i]     = h01;
    ((__half2*)g_hhi)[2 * i + 1] = h23;
    ((__half2*)g_hlo)[2 * i]     = __floats2half2_rn(v.x - f01.x, v.y - f01.y);
    ((__half2*)g_hlo)[2 * i + 1] = __floats2half2_rn(v.z - f23.x, v.w - f23.y);
}

__global__ void zero_kernel(float* __restrict__ out) {
    int i = blockIdx.x * blockDim.x + threadIdx.x;
    if (i < TOKENS * HIDDEN) out[i] = 0.0f;
}

// ================ GEMM1: gate+up, fp16 2-term (A hi/lo, B hi-only) ==============
// BM=128, BN=64, BK=16, 256 thr, 4(m)x2(n) warps, 2-stage, 2 CTAs/SM.
// Stage: Ahi 6144 | Alo 6144 | Bgh 2304 | Buh 2304 = 16896
#define LDA 24
#define LDB 72
#define G1_STG  16896
#define G1_SMEM (512 + 2 * G1_STG)   // 34304

__global__ __launch_bounds__(256, 2) void gemm1_wmma(
    const float* __restrict__ wg,
    const float* __restrict__ wu)
{
    const int e   = blockIdx.z;
    const int cnt = g_count[e];
    const int m0  = blockIdx.y * 128;
    if (m0 >= cnt) return;
    const int n0   = blockIdx.x * 64;
    const int base = g_offset[e];

    extern __shared__ char sm[];
    int* toks = (int*)sm;

    const int tid  = threadIdx.x;
    const int wid  = tid >> 5, lane = tid & 31;
    const int wm   = (wid & 3) * 32;
    const int wn   = (wid >> 2) * 32;

    if (tid < 128) {
        int r = m0 + tid;
        toks[tid] = g_tok[base + ((r < cnt) ? r : 0)];
    }
    __syncthreads();

    FragC accg[2][2], accu[2][2];
#pragma unroll
    for (int mt = 0; mt < 2; mt++)
#pragma unroll
        for (int nt = 0; nt < 2; nt++) {
            wmma::fill_fragment(accg[mt][nt], 0.0f);
            wmma::fill_fragment(accu[mt][nt], 0.0f);
        }

    const int ar = tid >> 1;
    const int aq = (tid & 1) * 8;
    const size_t arowoff = (size_t)toks[ar] * HIDDEN + aq;
    const int brow = tid >> 4, bc4 = (tid & 15) * 4;

    uint4 pfAh, pfAl;
    float4 pfG, pfU;

    auto LOADG = [&](int k0) {
        pfAh = *(const uint4*)(g_hhi + arowoff + k0);
        pfAl = *(const uint4*)(g_hlo + arowoff + k0);
        size_t off = (size_t)e * HIDDEN * INTER + (size_t)(k0 + brow) * INTER + n0 + bc4;
        pfG = *(const float4*)(wg + off);
        pfU = *(const float4*)(wu + off);
    };
    auto STORES = [&](int b) {
        char* st = sm + 512 + b * G1_STG;
        __half* Ahi = (__half*)(st);
        __half* Alo = (__half*)(st + 6144);
        __half* Bgh = (__half*)(st + 12288);
        __half* Buh = (__half*)(st + 14592);
        *(uint4*)(Ahi + ar * LDA + aq) = pfAh;
        *(uint4*)(Alo + ar * LDA + aq) = pfAl;
        cvt4h(pfG, Bgh + brow * LDB + bc4);
        cvt4h(pfU, Buh + brow * LDB + bc4);
    };

    const int NS = HIDDEN / 16;   // 128
    LOADG(0);
    STORES(0);
    LOADG(16);
    __syncthreads();

    for (int s = 0; s < NS; s++) {
        if (s + 1 < NS) STORES((s + 1) & 1);
        if (s + 2 < NS) LOADG((s + 2) * 16);

        const char* st = sm + 512 + (s & 1) * G1_STG;
        const __half* Ahi = (const __half*)(st);
        const __half* Alo = (const __half*)(st + 6144);
        const __half* Bgh = (const __half*)(st + 12288);
        const __half* Buh = (const __half*)(st + 14592);

        HFragA ah[2], al[2];
#pragma unroll
        for (int mt = 0; mt < 2; mt++) {
            wmma::load_matrix_sync(ah[mt], Ahi + (wm + mt * 16) * LDA, LDA);
            wmma::load_matrix_sync(al[mt], Alo + (wm + mt * 16) * LDA, LDA);
        }
#pragma unroll
        for (int nt = 0; nt < 2; nt++) {
            HFragB bg, bu;
            const int bcol = wn + nt * 16;
            wmma::load_matrix_sync(bg, Bgh + bcol, LDB);
            wmma::load_matrix_sync(bu, Buh + bcol, LDB);
#pragma unroll
            for (int mt = 0; mt < 2; mt++) {
                wmma::mma_sync(accg[mt][nt], ah[mt], bg, accg[mt][nt]);
                wmma::mma_sync(accg[mt][nt], al[mt], bg, accg[mt][nt]);
                wmma::mma_sync(accu[mt][nt], ah[mt], bu, accu[mt][nt]);
                wmma::mma_sync(accu[mt][nt], al[mt], bu, accu[mt][nt]);
            }
        }
        __syncthreads();
    }

    // epilogue: swiglu + bf16 hi/lo activation store
    float* stg = (float*)(sm + 512) + wid * 320;
#pragma unroll
    for (int mt = 0; mt < 2; mt++)
#pragma unroll
        for (int nt = 0; nt < 2; nt++) {
            FragC& G = accg[mt][nt];
            FragC& U = accu[mt][nt];
#pragma unroll
            for (int i = 0; i < G.num_elements; i++) {
                float g = G.x[i];
                G.x[i] = (g / (1.0f + __expf(-g))) * U.x[i];
            }
            wmma::store_matrix_sync(stg, G, 20, wmma::mem_row_major);
            __syncwarp();
            for (int i = lane; i < 128; i += 32) {
                int r = i >> 3, c = (i & 7) * 2;
                int m = m0 + wm + mt * 16 + r;
                if (m < cnt) {
                    float a0 = stg[r * 20 + c], a1 = stg[r * 20 + c + 1];
                    __nv_bfloat162 hv = __floats2bfloat162_rn(a0, a1);
                    float2 hf = __bfloat1622float2(hv);
                    __nv_bfloat162 lv = __floats2bfloat162_rn(a0 - hf.x, a1 - hf.y);
                    size_t off = (size_t)(base + m) * INTER + n0 + wn + nt * 16 + c;
                    *(__nv_bfloat162*)(g_ahi + off) = hv;
                    *(__nv_bfloat162*)(g_alo + off) = lv;
                }
            }
            __syncwarp();
        }
}

// ================ GEMM2: down (R12-proven), bf16x3, BN=128, atomics =============
#define LDB2 136
#define G2_STG  20992
#define G2_SMEM (2 * G2_STG)

__global__ __launch_bounds__(256, 2) void gemm2_wmma(
    const float* __restrict__ wd, float* __restrict__ out)
{
    const int e   = blockIdx.z;
    const int cnt = g_count[e];
    const int m0  = blockIdx.y * 128;
    if (m0 >= cnt) return;
    const int n0   = blockIdx.x * 128;
    const int base = g_offset[e];

    extern __shared__ char sm[];

    const int tid  = threadIdx.x;
    const int wid  = tid >> 5, lane = tid & 31;
    const int wm   = (wid & 3) * 32;
    const int wn   = (wid >> 2) * 64;

    const int ar = tid >> 1;
    const int aq = (tid & 1) * 8;
    int arm = m0 + ar;
    const int arow = base + ((arm < cnt) ? arm : 0);
    const int brow = tid >> 4, bc8 = (tid & 15) * 8;

    FragC acc[2][4];
#pragma unroll
    for (int mt = 0; mt < 2; mt++)
#pragma unroll
        for (int nt = 0; nt < 4; nt++) wmma::fill_fragment(acc[mt][nt], 0.0f);

    uint4 pfAh, pfAl;
    float4 pfB0, pfB1;

    auto LOADG = [&](int k0) {
        size_t off = (size_t)arow * INTER + k0 + aq;
        pfAh = *(const uint4*)(g_ahi + off);
        pfAl = *(const uint4*)(g_alo + off);
        const float* bsrc = wd + (size_t)e * INTER * HIDDEN + (size_t)(k0 + brow) * HIDDEN + n0 + bc8;
        pfB0 = *(const float4*)(bsrc);
        pfB1 = *(const float4*)(bsrc + 4);
    };
    auto STORES = [&](int b) {
        char* st = sm + b * G2_STG;
        __nv_bfloat16* Ahi = (__nv_bfloat16*)(st);
        __nv_bfloat16* Alo = (__nv_bfloat16*)(st + 6144);
        __nv_bfloat16* Bh  = (__nv_bfloat16*)(st + 12288);
        __nv_bfloat16* Bl  = (__nv_bfloat16*)(st + 16640);
        *(uint4*)(Ahi + ar * LDA + aq) = pfAh;
        *(uint4*)(Alo + ar * LDA + aq) = pfAl;
        split4s(pfB0, Bh + brow * LDB2 + bc8,     Bl + brow * LDB2 + bc8);
        split4s(pfB1, Bh + brow * LDB2 + bc8 + 4, Bl + brow * LDB2 + bc8 + 4);
    };

    const int NS = INTER / 16;   // 88
    LOADG(0);
    STORES(0);
    LOADG(16);
    __syncthreads();

    for (int s = 0; s < NS; s++) {
        if (s + 1 < NS) STORES((s + 1) & 1);
        if (s + 2 < NS) LOADG((s + 2) * 16);

        const char* st = sm + (s & 1) * G2_STG;
        const __nv_bfloat16* Ahi = (const __nv_bfloat16*)(st);
        const __nv_bfloat16* Alo = (const __nv_bfloat16*)(st + 6144);
        const __nv_bfloat16* Bh  = (const __nv_bfloat16*)(st + 12288);
        const __nv_bfloat16* Bl  = (const __nv_bfloat16*)(st + 16640);

        FragA ah[2], al[2];
#pragma unroll
        for (int mt = 0; mt < 2; mt++) {
            wmma::load_matrix_sync(ah[mt], Ahi + (wm + mt * 16) * LDA, LDA);
            wmma::load_matrix_sync(al[mt], Alo + (wm + mt * 16) * LDA, LDA);
        }
#pragma unroll
        for (int nt = 0; nt < 4; nt++) {
            FragB bh, bl;
            const int bcol = wn + nt * 16;
            wmma::load_matrix_sync(bh, Bh + bcol, LDB2);
            wmma::load_matrix_sync(bl, Bl + bcol, LDB2);
#pragma unroll
            for (int mt = 0; mt < 2; mt++) {
                wmma::mma_sync(acc[mt][nt], ah[mt], bh, acc[mt][nt]);
                wmma::mma_sync(acc[mt][nt], al[mt], bh, acc[mt][nt]);
                wmma::mma_sync(acc[mt][nt], ah[mt], bl, acc[mt][nt]);
            }
        }
        __syncthreads();
    }

    // weighted scatter via per-warp staging
    float* stg = (float*)sm + wid * 320;
#pragma unroll
    for (int mt = 0; mt < 2; mt++)
#pragma unroll
        for (int nt = 0; nt < 4; nt++) {
            wmma::store_matrix_sync(stg, acc[mt][nt], 20, wmma::mem_row_major);
            __syncwarp();
            for (int i = lane; i < 256; i += 32) {
                int r = i >> 4, c = i & 15;
                int m = m0 + wm + mt * 16 + r;
                if (m < cnt) {
                    int   t = g_tok[base + m];
                    float w = g_w[base + m];
                    atomicAdd(out + (size_t)t * HIDDEN + n0 + wn + nt * 16 + c,
                              w * stg[r * 20 + c]);
                }
            }
            __syncwarp();
        }
}

// ---------------- launch ------------------------------------------------------------
extern "C" void kernel_launch(void* const* d_in, const int* in_sizes, int n_in,
                              void* d_out, int out_size) {
    (void)in_sizes; (void)n_in; (void)out_size;
    const float* hidden = (const float*)d_in[0];
    const float* logits = (const float*)d_in[1];
    const float* wg     = (const float*)d_in[2];
    const float* wu     = (const float*)d_in[3];
    const float* wd     = (const float*)d_in[4];
    float* out = (float*)d_out;

    route_kernel<<<(TOKENS + 255) / 256, 256>>>(logits);                  // 0
    scanplace_kernel<<<1, 1024>>>();                                      // 1
    conv_hidden<<<(TOKENS * HIDDEN / 4 + 255) / 256, 256>>>((const float4*)hidden); // 2

    dim3 g1(INTER / 64, (TOKENS + 127) / 128, NE);    // (22, 32, 16)
    gemm1_wmma<<<g1, 256, G1_SMEM>>>(wg, wu);                             // 3 (profiled)

    zero_kernel<<<(TOKENS * HIDDEN + 255) / 256, 256>>>(out);             // 4
    dim3 g2(HIDDEN / 128, (TOKENS + 127) / 128, NE);  // (16, 32, 16)
    gemm2_wmma<<<g2, 256, G2_SMEM>>>(wd, out);                            // 5
}